// round 4
// baseline (speedup 1.0000x reference)
#include <cuda_runtime.h>
#include <cstdint>

#define BB 8
#define TT 2048
#define DD 256
#define HH 4
#define HDIM 64
#define NT (BB*TT)           // 16384 rows
#define NEGV (-1e9f)
#define EPSV 1e-5f
#define MQ 16                // queries per attention block

// ---------------- device scratch -------------------------------------------
__device__ float g_Q[BB*HH*TT*HDIM];
__device__ float g_K[BB*HH*TT*HDIM];
__device__ float g_V[BB*HH*TT*HDIM];
__device__ float g_attn[NT*DD];
__device__ unsigned char g_pad[NT];

// ---------------- packed fp32x2 helpers -------------------------------------
union F2U { unsigned long long u; float2 f; };

__device__ __forceinline__ void ffma2(unsigned long long& acc,
                                      unsigned long long a, unsigned long long b) {
    asm("fma.rn.f32x2 %0, %1, %2, %0;" : "+l"(acc) : "l"(a), "l"(b));
}
__device__ __forceinline__ float hsum2(unsigned long long u) {
    F2U t; t.u = u; return t.f.x + t.f.y;
}

// ---------------- mask dtype detection + expansion --------------------------
__global__ void mask_prep_kernel(const void* __restrict__ maskraw) {
    __shared__ int cntOff, cnt3F, mode;
    const unsigned char* b = (const unsigned char*)maskraw;
    int tid = threadIdx.x;
    if (tid == 0) { cntOff = 0; cnt3F = 0; }
    __syncthreads();
    int lo = 0, l3 = 0;
    for (int i = tid; i < NT; i += blockDim.x) {
        unsigned char v = b[i];
        if ((i & 3) != 0 && v != 0) lo++;
        if ((i & 3) == 3 && v == 0x3F) l3++;
    }
    atomicAdd(&cntOff, lo);
    atomicAdd(&cnt3F, l3);
    __syncthreads();
    if (tid == 0) {
        if (cnt3F > 0) mode = 2;            // float32
        else if (cntOff > 0) mode = 0;      // uint8 / bool
        else mode = 1;                      // int32
    }
    __syncthreads();
    int m = mode;
    for (int i = tid; i < NT; i += blockDim.x) {
        unsigned char p;
        if (m == 0)      p = (b[i] != 0);
        else if (m == 1) p = (((const int*)maskraw)[i] != 0);
        else             p = (((const float*)maskraw)[i] != 0.0f);
        g_pad[i] = p;
    }
}

// ---------------- QKV projection: y = x @ W^T, scattered to (B,H,T,hd) ------
__global__ __launch_bounds__(256)
void qkv_proj_kernel(const float* __restrict__ x,
                     const float* __restrict__ Wq,
                     const float* __restrict__ Wk,
                     const float* __restrict__ Wv) {
    __shared__ float4 Xs4[512];   // 64 rows x 8 chunks
    __shared__ float4 Ws4[512];
    const float* W = (blockIdx.z == 0) ? Wq : (blockIdx.z == 1 ? Wk : Wv);
    float* O       = (blockIdx.z == 0) ? g_Q : (blockIdx.z == 1 ? g_K : g_V);
    int n0 = blockIdx.x * 64;
    int h  = blockIdx.y;
    int j0 = h * 64;
    int tid = threadIdx.x;
    int tx = tid & 15, ty = tid >> 4;

    int f0 = tid * 2;
    int lr = f0 >> 3, lc = f0 & 7;
    int wxor = ((lr >> 2) & 7) ^ ((lr & 3) << 1);

    const float4* xg = (const float4*)&x[(size_t)(n0 + lr) * DD];
    const float4* wg = (const float4*)&W[(size_t)(j0 + lr) * DD];
    float4 px0 = xg[lc], px1 = xg[lc + 1];
    float4 pw0 = wg[lc], pw1 = wg[lc + 1];

    unsigned long long acc[4][4] = {};

    for (int kk = 0; kk < DD; kk += 32) {
        __syncthreads();
        Xs4[lr * 8 + lc]              = px0;
        Xs4[lr * 8 + lc + 1]          = px1;
        Ws4[lr * 8 + (lc ^ wxor)]     = pw0;
        Ws4[lr * 8 + ((lc + 1) ^ wxor)] = pw1;
        if (kk + 32 < DD) {
            int o = (kk + 32) >> 2;
            px0 = xg[o + lc]; px1 = xg[o + lc + 1];
            pw0 = wg[o + lc]; pw1 = wg[o + lc + 1];
        }
        __syncthreads();
        #pragma unroll
        for (int c = 0; c < 8; c++) {
            ulonglong2 xs[4], ws[4];
            #pragma unroll
            for (int i = 0; i < 4; i++)
                xs[i] = *(const ulonglong2*)&Xs4[(ty * 4 + i) * 8 + c];
            #pragma unroll
            for (int j = 0; j < 4; j++)
                ws[j] = *(const ulonglong2*)&Ws4[(tx * 4 + j) * 8 +
                                                 (c ^ (tx & 7) ^ (j << 1))];
            #pragma unroll
            for (int i = 0; i < 4; i++)
                #pragma unroll
                for (int j = 0; j < 4; j++) {
                    ffma2(acc[i][j], xs[i].x, ws[j].x);
                    ffma2(acc[i][j], xs[i].y, ws[j].y);
                }
        }
    }
    #pragma unroll
    for (int i = 0; i < 4; i++) {
        int n = n0 + ty * 4 + i;
        int bi = n >> 11, t = n & (TT - 1);
        float* orow = O + (((size_t)bi * HH + h) * TT + t) * HDIM + tx * 4;
        float4 v = make_float4(hsum2(acc[i][0]), hsum2(acc[i][1]),
                               hsum2(acc[i][2]), hsum2(acc[i][3]));
        *(float4*)orow = v;
    }
}

// ---------------- fused attention: 512 threads, 16 warps --------------------
// smem (floats): sQ[0..1024) 16x64 ; sS[1024..33792) 16x2048 ;
// sK[33792..50176) two 128-key swizzled tiles (rep0, rep1); aliased by sIdx
// then sMask 2048 B, sCnt 16 ints
#define SMEM_ATTN_BYTES ((1024 + 32768 + 16384) * 4 + 2048 + 64)

__global__ __launch_bounds__(512)
void attn_kernel() {
    extern __shared__ unsigned char smraw[];
    float* sQ = (float*)smraw;
    float* sS = sQ + 1024;
    float* sK = sS + 32768;
    float4* sK4 = (float4*)sK;
    unsigned short* sIdx = (unsigned short*)sK;         // aliases sK (64KB)
    unsigned char* sMask = (unsigned char*)(sK + 16384);
    int* sCnt = (int*)(sMask + 2048);

    int tid = threadIdx.x;
    int qt = blockIdx.x, h = blockIdx.y, b = blockIdx.z;
    int t0 = qt * MQ;
    const float* Qb = g_Q + (((size_t)b * HH + h) * TT) * HDIM;
    const float* Kb = g_K + (((size_t)b * HH + h) * TT) * HDIM;
    const float* Vb = g_V + (((size_t)b * HH + h) * TT) * HDIM;

    // ---- Q tile (pre-scaled by 1/sqrt(hd)) + mask ----
    if (tid < 256) {
        int q = tid >> 4, d4 = (tid & 15) << 2;
        float4 v = *(const float4*)&Qb[(t0 + q) * HDIM + d4];
        const float inv = 0.125f;
        sQ[q * HDIM + d4 + 0] = v.x * inv;
        sQ[q * HDIM + d4 + 1] = v.y * inv;
        sQ[q * HDIM + d4 + 2] = v.z * inv;
        sQ[q * HDIM + d4 + 3] = v.w * inv;
    }
    for (int i = tid; i < TT; i += 512) sMask[i] = g_pad[b * TT + i];

    // ---- phase 2: scores, two halves (rep) on interleaved 128-key tiles ----
    int rep = tid >> 8;          // 0,1
    int rt  = tid & 255;
    int kg  = rt & 63;           // 2 keys each
    int qg  = rt >> 6;           // 4 query rows each
    const float4* Kg4 = (const float4*)Kb;
    float4* myK = sK4 + rep * 2048;

    float4 pre[8];
    int kb = rep * 128;
    {
        const float4* base = Kg4 + (size_t)kb * 16;
        #pragma unroll
        for (int s = 0; s < 8; s++) pre[s] = base[rt + s * 256];
    }

    for (int t = 0; t < 8; t++) {
        __syncthreads();
        #pragma unroll
        for (int s = 0; s < 8; s++) {
            int fi = rt + s * 256;
            int key = fi >> 4, cc = fi & 15;
            int xr = ((key >> 1) & 7) ^ ((key & 1) << 2);
            myK[(fi & ~15) | (cc ^ xr)] = pre[s];
        }
        if (t < 7) {
            const float4* base = Kg4 + (size_t)(kb + 256) * 16;
            #pragma unroll
            for (int s = 0; s < 8; s++) pre[s] = base[rt + s * 256];
        }
        __syncthreads();

        unsigned long long acc[4][2] = {};
        #pragma unroll 8
        for (int c = 0; c < 16; c++) {
            ulonglong2 q[4];
            #pragma unroll
            for (int i = 0; i < 4; i++)
                q[i] = *(const ulonglong2*)&sQ[(qg * 4 + i) * HDIM + c * 4];
            #pragma unroll
            for (int j = 0; j < 2; j++) {
                ulonglong2 kv = *(const ulonglong2*)
                    &myK[(kg * 2 + j) * 16 + (c ^ (kg & 7) ^ (j << 2))];
                #pragma unroll
                for (int i = 0; i < 4; i++) {
                    ffma2(acc[i][j], q[i].x, kv.x);
                    ffma2(acc[i][j], q[i].y, kv.y);
                }
            }
        }
        #pragma unroll
        for (int i = 0; i < 4; i++) {
            float2 v = make_float2(hsum2(acc[i][0]), hsum2(acc[i][1]));
            *(float2*)&sS[(qg * 4 + i) * TT + kb + kg * 2] = v;
        }
        kb += 256;
    }
    __syncthreads();

    // ---- phase 3: sparsemax, 1 warp : 1 row ----
    int wid = tid >> 5, lane = tid & 31;
    {
        int row = wid;
        float z[64];
        float zmax = -3e38f;
        #pragma unroll
        for (int i = 0; i < 64; i++) {
            int k = i * 32 + lane;
            float v = sMask[k] ? NEGV : sS[row * TT + k];
            z[i] = v;
            zmax = fmaxf(zmax, v);
        }
        #pragma unroll
        for (int o = 16; o; o >>= 1) zmax = fmaxf(zmax, __shfl_xor_sync(0xffffffffu, zmax, o));
        float tau = zmax - 1.0f;
        for (int it = 0; it < 24; it++) {
            float s = 0.f, c = 0.f;
            #pragma unroll
            for (int i = 0; i < 64; i++) {
                if (z[i] > tau) { s += z[i]; c += 1.0f; }
            }
            #pragma unroll
            for (int o = 16; o; o >>= 1) {
                s += __shfl_xor_sync(0xffffffffu, s, o);
                c += __shfl_xor_sync(0xffffffffu, c, o);
            }
            float nt = (s - 1.0f) / c;
            if (nt == tau) break;
            tau = nt;
        }
        unsigned cnt = 0;
        #pragma unroll
        for (int i = 0; i < 64; i++) {
            float w = z[i] - tau;
            bool p = w > 0.f;
            sS[row * TT + i * 32 + lane] = p ? w : 0.f;
            unsigned m = __ballot_sync(0xffffffffu, p);
            if (p) {
                int pos = cnt + __popc(m & ((1u << lane) - 1u));
                sIdx[row * 2048 + pos] = (unsigned short)(i * 32 + lane);
            }
            cnt += __popc(m);
        }
        if (lane == 0) sCnt[row] = (int)cnt;
    }
    __syncthreads();

    // ---- phase 4: sparse A @ V, 32 threads per query ----
    {
        int q  = tid >> 5;         // 0..15
        int dg = lane & 15;        // 4 dims
        int ep = lane >> 4;        // entry parity
        int n = sCnt[q];
        float4 acc = make_float4(0.f, 0.f, 0.f, 0.f);
        int j = ep;
        for (; j + 2 < n; j += 4) {
            int k0 = sIdx[q * 2048 + j];
            int k1 = sIdx[q * 2048 + j + 2];
            float w0 = sS[q * TT + k0];
            float w1 = sS[q * TT + k1];
            float4 v0 = *(const float4*)&Vb[(size_t)k0 * HDIM + dg * 4];
            float4 v1 = *(const float4*)&Vb[(size_t)k1 * HDIM + dg * 4];
            acc.x += w0 * v0.x + w1 * v1.x;
            acc.y += w0 * v0.y + w1 * v1.y;
            acc.z += w0 * v0.z + w1 * v1.z;
            acc.w += w0 * v0.w + w1 * v1.w;
        }
        if (j < n) {
            int k = sIdx[q * 2048 + j];
            float w = sS[q * TT + k];
            float4 v = *(const float4*)&Vb[(size_t)k * HDIM + dg * 4];
            acc.x += w * v.x; acc.y += w * v.y; acc.z += w * v.z; acc.w += w * v.w;
        }
        acc.x += __shfl_xor_sync(0xffffffffu, acc.x, 16);
        acc.y += __shfl_xor_sync(0xffffffffu, acc.y, 16);
        acc.z += __shfl_xor_sync(0xffffffffu, acc.z, 16);
        acc.w += __shfl_xor_sync(0xffffffffu, acc.w, 16);
        if (ep == 0)
            *(float4*)&g_attn[((size_t)b * TT + t0 + q) * DD + h * HDIM + dg * 4] = acc;
    }
}

// ---------------- out-proj + residual + LayerNorm ---------------------------
__global__ __launch_bounds__(256)
void outproj_ln_kernel(const float* __restrict__ x,
                       const float* __restrict__ Wo,
                       const float* __restrict__ gamma,
                       const float* __restrict__ beta,
                       float* __restrict__ out) {
    __shared__ float sA[16][DD];
    __shared__ float sY[16][DD + 1];
    __shared__ float sMu[16], sRs[16];
    int n0 = blockIdx.x * 16;
    int tid = threadIdx.x;              // output column j

    for (int i = tid; i < 16 * 64; i += 256) {
        int r = i >> 6, c4 = (i & 63) * 4;
        *(float4*)&sA[r][c4] = *(const float4*)&g_attn[((size_t)n0 + r) * DD + c4];
    }
    __syncthreads();

    unsigned long long acc2[16] = {};
    const ulonglong2* wrow = (const ulonglong2*)(Wo + (size_t)tid * DD);
    #pragma unroll 4
    for (int c = 0; c < 64; c++) {
        ulonglong2 w = wrow[c];
        #pragma unroll
        for (int r = 0; r < 16; r++) {
            ulonglong2 a = *(const ulonglong2*)&sA[r][c * 4];
            ffma2(acc2[r], w.x, a.x);
            ffma2(acc2[r], w.y, a.y);
        }
    }
    #pragma unroll
    for (int r = 0; r < 16; r++)
        sY[r][tid] = hsum2(acc2[r]) + x[((size_t)n0 + r) * DD + tid];
    __syncthreads();

    int wid = tid >> 5, lane = tid & 31;
    for (int rr = 0; rr < 2; rr++) {
        int r = wid * 2 + rr;
        float s = 0.f, s2 = 0.f;
        #pragma unroll
        for (int i = 0; i < 8; i++) {
            float v = sY[r][lane * 8 + i];
            s += v; s2 += v * v;
        }
        #pragma unroll
        for (int o = 16; o; o >>= 1) {
            s  += __shfl_xor_sync(0xffffffffu, s, o);
            s2 += __shfl_xor_sync(0xffffffffu, s2, o);
        }
        if (lane == 0) {
            float mu = s * (1.0f / DD);
            sMu[r] = mu;
            sRs[r] = rsqrtf(s2 * (1.0f / DD) - mu * mu + EPSV);
        }
    }
    __syncthreads();
    float g = gamma[tid], bt = beta[tid];
    #pragma unroll
    for (int r = 0; r < 16; r++)
        out[((size_t)n0 + r) * DD + tid] = (sY[r][tid] - sMu[r]) * sRs[r] * g + bt;
}

// ---------------- launch ----------------------------------------------------
extern "C" void kernel_launch(void* const* d_in, const int* in_sizes, int n_in,
                              void* d_out, int out_size) {
    const float* x     = (const float*)d_in[0];
    const void*  mask  = d_in[1];
    const float* Wq    = (const float*)d_in[2];
    const float* Wk    = (const float*)d_in[3];
    const float* Wv    = (const float*)d_in[4];
    const float* Wo    = (const float*)d_in[5];
    const float* gamma = (const float*)d_in[6];
    const float* beta  = (const float*)d_in[7];
    float* out = (float*)d_out;

    cudaFuncSetAttribute(attn_kernel, cudaFuncAttributeMaxDynamicSharedMemorySize,
                         SMEM_ATTN_BYTES);

    mask_prep_kernel<<<1, 256>>>(mask);
    qkv_proj_kernel<<<dim3(NT / 64, HH, 3), 256>>>(x, Wq, Wk, Wv);
    attn_kernel<<<dim3(TT / MQ, HH, BB), 512, SMEM_ATTN_BYTES>>>();
    outproj_ln_kernel<<<NT / 16, 256>>>(x, Wo, gamma, beta, out);
}

// round 8
// speedup vs baseline: 1.9948x; 1.9948x over previous
#include <cuda_runtime.h>
#include <cstdint>

#define BB 8
#define TT 2048
#define DD 256
#define HH 4
#define HDIM 64
#define NT (BB*TT)           // 16384 rows
#define NROWS (BB*HH*TT)     // 65536 attention score rows
#define NEGV (-1e9f)
#define EPSV 1e-5f

// ---------------- device scratch (module-load allocated) --------------------
__device__ float g_Q[BB*HH*TT*HDIM];
__device__ float g_K[BB*HH*TT*HDIM];
__device__ float g_V[BB*HH*TT*HDIM];
__device__ float g_S[(size_t)BB*HH*TT*TT];   // 512 MiB score scratch
__device__ float g_attn[NT*DD];
__device__ unsigned char g_pad[NT];

// ---------------- packed fp32x2 helpers -------------------------------------
union F2U { unsigned long long u; float2 f; };

__device__ __forceinline__ void ffma2(unsigned long long& acc,
                                      unsigned long long a, unsigned long long b) {
    asm("fma.rn.f32x2 %0, %1, %2, %0;" : "+l"(acc) : "l"(a), "l"(b));
}
__device__ __forceinline__ float hsum2(unsigned long long u) {
    F2U t; t.u = u; return t.f.x + t.f.y;
}

// ---------------- mask dtype detection + expansion --------------------------
__global__ void mask_prep_kernel(const void* __restrict__ maskraw) {
    __shared__ int cntOff, cnt3F, mode;
    const unsigned char* b = (const unsigned char*)maskraw;
    int tid = threadIdx.x;
    if (tid == 0) { cntOff = 0; cnt3F = 0; }
    __syncthreads();
    int lo = 0, l3 = 0;
    for (int i = tid; i < NT; i += blockDim.x) {
        unsigned char v = b[i];
        if ((i & 3) != 0 && v != 0) lo++;
        if ((i & 3) == 3 && v == 0x3F) l3++;
    }
    atomicAdd(&cntOff, lo);
    atomicAdd(&cnt3F, l3);
    __syncthreads();
    if (tid == 0) {
        if (cnt3F > 0) mode = 2;            // float32
        else if (cntOff > 0) mode = 0;      // uint8 / bool
        else mode = 1;                      // int32
    }
    __syncthreads();
    int m = mode;
    for (int i = tid; i < NT; i += blockDim.x) {
        unsigned char p;
        if (m == 0)      p = (b[i] != 0);
        else if (m == 1) p = (((const int*)maskraw)[i] != 0);
        else             p = (((const float*)maskraw)[i] != 0.0f);
        g_pad[i] = p;
    }
}

// ---------------- QKV projection (round-2 known-good) ------------------------
__global__ __launch_bounds__(256)
void qkv_proj_kernel(const float* __restrict__ x,
                     const float* __restrict__ Wq,
                     const float* __restrict__ Wk,
                     const float* __restrict__ Wv) {
    __shared__ float4 Xs4[512];   // 64 rows x 8 chunks
    __shared__ float4 Ws4[512];
    const float* W = (blockIdx.z == 0) ? Wq : (blockIdx.z == 1 ? Wk : Wv);
    float* O       = (blockIdx.z == 0) ? g_Q : (blockIdx.z == 1 ? g_K : g_V);
    int n0 = blockIdx.x * 64;
    int h  = blockIdx.y;
    int j0 = h * 64;
    int tid = threadIdx.x;
    int tx = tid & 15, ty = tid >> 4;

    int f0 = tid * 2;
    int lr = f0 >> 3, lc = f0 & 7;
    int wxor = ((lr >> 2) & 7) ^ ((lr & 3) << 1);

    const float4* xg = (const float4*)&x[(size_t)(n0 + lr) * DD];
    const float4* wg = (const float4*)&W[(size_t)(j0 + lr) * DD];
    float4 px0 = xg[lc], px1 = xg[lc + 1];
    float4 pw0 = wg[lc], pw1 = wg[lc + 1];

    unsigned long long acc[4][4] = {};

    for (int kk = 0; kk < DD; kk += 32) {
        __syncthreads();
        Xs4[lr * 8 + lc]              = px0;
        Xs4[lr * 8 + lc + 1]          = px1;
        Ws4[lr * 8 + (lc ^ wxor)]     = pw0;
        Ws4[lr * 8 + ((lc + 1) ^ wxor)] = pw1;
        if (kk + 32 < DD) {
            int o = (kk + 32) >> 2;
            px0 = xg[o + lc]; px1 = xg[o + lc + 1];
            pw0 = wg[o + lc]; pw1 = wg[o + lc + 1];
        }
        __syncthreads();
        #pragma unroll
        for (int c = 0; c < 8; c++) {
            ulonglong2 xs[4], ws[4];
            #pragma unroll
            for (int i = 0; i < 4; i++)
                xs[i] = *(const ulonglong2*)&Xs4[(ty * 4 + i) * 8 + c];
            #pragma unroll
            for (int j = 0; j < 4; j++)
                ws[j] = *(const ulonglong2*)&Ws4[(tx * 4 + j) * 8 +
                                                 (c ^ (tx & 7) ^ (j << 1))];
            #pragma unroll
            for (int i = 0; i < 4; i++)
                #pragma unroll
                for (int j = 0; j < 4; j++) {
                    ffma2(acc[i][j], xs[i].x, ws[j].x);
                    ffma2(acc[i][j], xs[i].y, ws[j].y);
                }
        }
    }
    #pragma unroll
    for (int i = 0; i < 4; i++) {
        int n = n0 + ty * 4 + i;
        int bi = n >> 11, t = n & (TT - 1);
        float* orow = O + (((size_t)bi * HH + h) * TT + t) * HDIM + tx * 4;
        float4 v = make_float4(hsum2(acc[i][0]), hsum2(acc[i][1]),
                               hsum2(acc[i][2]), hsum2(acc[i][3]));
        *(float4*)orow = v;
    }
}

// ---------------- score GEMM: S = (Q/8) K^T, 128q x 64k tiles ---------------
// 256 threads, 8q x 4k per thread, FMA2 over d. Smem chunk-XOR swizzle
// (chunk ^ ((row>>2)&7)) -> conflict-free stores and strided reads.
__global__ __launch_bounds__(256, 2)
void score_kernel() {
    __shared__ float4 sQ4[128 * 16];   // 32 KB
    __shared__ float4 sK4[64 * 16];    // 16 KB
    int tid = threadIdx.x;
    int kt = blockIdx.x & 31;          // 32 tiles of 64 keys
    int qt = blockIdx.x >> 5;          // 16 tiles of 128 queries
    int h = blockIdx.y, b = blockIdx.z;

    const float4* Qg = (const float4*)(g_Q + ((size_t)(b * HH + h) * TT + qt * 128) * HDIM);
    const float4* Kg = (const float4*)(g_K + ((size_t)(b * HH + h) * TT + kt * 64) * HDIM);

    #pragma unroll
    for (int s = 0; s < 8; s++) {
        int idx = s * 256 + tid;
        int r = idx >> 4, c = idx & 15;
        float4 v = Qg[idx];
        v.x *= 0.125f; v.y *= 0.125f; v.z *= 0.125f; v.w *= 0.125f;
        sQ4[r * 16 + (c ^ ((r >> 2) & 7))] = v;
    }
    #pragma unroll
    for (int s = 0; s < 4; s++) {
        int idx = s * 256 + tid;
        int r = idx >> 4, c = idx & 15;
        sK4[r * 16 + (c ^ ((r >> 2) & 7))] = Kg[idx];
    }
    __syncthreads();

    int tx = tid & 15, ty = tid >> 4;   // tx -> 4 keys, ty -> 8 queries
    unsigned long long acc[8][4] = {};
    #pragma unroll 4
    for (int c = 0; c < 16; c++) {
        ulonglong2 qf[8], kf[4];
        #pragma unroll
        for (int i = 0; i < 8; i++) {
            int r = ty * 8 + i;
            qf[i] = *(const ulonglong2*)&sQ4[r * 16 + (c ^ ((r >> 2) & 7))];
        }
        #pragma unroll
        for (int j = 0; j < 4; j++) {
            int r = tx * 4 + j;
            kf[j] = *(const ulonglong2*)&sK4[r * 16 + (c ^ ((r >> 2) & 7))];
        }
        #pragma unroll
        for (int i = 0; i < 8; i++)
            #pragma unroll
            for (int j = 0; j < 4; j++) {
                ffma2(acc[i][j], qf[i].x, kf[j].x);
                ffma2(acc[i][j], qf[i].y, kf[j].y);
            }
    }

    float* Sout = g_S + ((size_t)(b * HH + h) * TT + qt * 128 + ty * 8) * TT
                + kt * 64 + tx * 4;
    #pragma unroll
    for (int i = 0; i < 8; i++) {
        float4 v = make_float4(hsum2(acc[i][0]), hsum2(acc[i][1]),
                               hsum2(acc[i][2]), hsum2(acc[i][3]));
        *(float4*)&Sout[(size_t)i * TT] = v;
    }
}

// ---------------- sparsemax + sparse AV: 1 warp per score row ---------------
__global__ __launch_bounds__(256)
void spmax_av_kernel() {
    int wid = threadIdx.x >> 5, lane = threadIdx.x & 31;
    int rid = blockIdx.x * 8 + wid;               // [0, NROWS)
    int b = rid >> 13, h = (rid >> 11) & 3, q = rid & 2047;

    const float4* Srow = (const float4*)(g_S + (size_t)rid * TT);
    const uchar4* pad4 = (const uchar4*)(g_pad + b * TT);

    // load row: z[it*4+j] holds key it*128 + lane*4 + j
    float z[64];
    float zmax = -3e38f;
    #pragma unroll
    for (int it = 0; it < 16; it++) {
        float4 sv = Srow[it * 32 + lane];
        uchar4 p = pad4[it * 32 + lane];
        float z0 = p.x ? NEGV : sv.x;
        float z1 = p.y ? NEGV : sv.y;
        float z2 = p.z ? NEGV : sv.z;
        float z3 = p.w ? NEGV : sv.w;
        z[it * 4 + 0] = z0; z[it * 4 + 1] = z1;
        z[it * 4 + 2] = z2; z[it * 4 + 3] = z3;
        zmax = fmaxf(fmaxf(fmaxf(zmax, z0), fmaxf(z1, z2)), z3);
    }
    #pragma unroll
    for (int o = 16; o; o >>= 1) zmax = fmaxf(zmax, __shfl_xor_sync(0xffffffffu, zmax, o));

    // Newton fixed point from tau0 = zmax - 1
    float tau = zmax - 1.0f;
    for (int it = 0; it < 24; it++) {
        float s = 0.f, c = 0.f;
        #pragma unroll
        for (int i = 0; i < 64; i++) {
            if (z[i] > tau) { s += z[i]; c += 1.0f; }
        }
        #pragma unroll
        for (int o = 16; o; o >>= 1) {
            s += __shfl_xor_sync(0xffffffffu, s, o);
            c += __shfl_xor_sync(0xffffffffu, c, o);
        }
        float nt = (s - 1.0f) / c;
        if (nt == tau) break;
        tau = nt;
    }

    // sparse AV: pop-loop over support, each lane accumulates 2 dims
    const float* Vb = g_V + ((size_t)(b * HH + h) * TT) * HDIM;
    float2 acc = make_float2(0.f, 0.f);
    #pragma unroll
    for (int g = 0; g < 16; g++) {
        #pragma unroll
        for (int j = 0; j < 4; j++) {
            float zz = z[g * 4 + j];
            unsigned m = __ballot_sync(0xffffffffu, zz > tau);
            while (m) {
                int src = __ffs(m) - 1;
                m &= m - 1;
                float w = __shfl_sync(0xffffffffu, zz, src) - tau;
                int k = g * 128 + src * 4 + j;
                float2 v = *(const float2*)&Vb[(size_t)k * HDIM + lane * 2];
                acc.x += w * v.x;
                acc.y += w * v.y;
            }
        }
    }
    *(float2*)&g_attn[((size_t)b * TT + q) * DD + h * HDIM + lane * 2] = acc;
}

// ---------------- out-proj + residual + LayerNorm (round-2 known-good) ------
__global__ __launch_bounds__(256)
void outproj_ln_kernel(const float* __restrict__ x,
                       const float* __restrict__ Wo,
                       const float* __restrict__ gamma,
                       const float* __restrict__ beta,
                       float* __restrict__ out) {
    __shared__ float sA[16][DD];
    __shared__ float sY[16][DD + 1];
    __shared__ float sMu[16], sRs[16];
    int n0 = blockIdx.x * 16;
    int tid = threadIdx.x;              // output column j

    for (int i = tid; i < 16 * 64; i += 256) {
        int r = i >> 6, c4 = (i & 63) * 4;
        *(float4*)&sA[r][c4] = *(const float4*)&g_attn[((size_t)n0 + r) * DD + c4];
    }
    __syncthreads();

    unsigned long long acc2[16] = {};
    const ulonglong2* wrow = (const ulonglong2*)(Wo + (size_t)tid * DD);
    #pragma unroll 4
    for (int c = 0; c < 64; c++) {
        ulonglong2 w = wrow[c];
        #pragma unroll
        for (int r = 0; r < 16; r++) {
            ulonglong2 a = *(const ulonglong2*)&sA[r][c * 4];
            ffma2(acc2[r], w.x, a.x);
            ffma2(acc2[r], w.y, a.y);
        }
    }
    #pragma unroll
    for (int r = 0; r < 16; r++)
        sY[r][tid] = hsum2(acc2[r]) + x[((size_t)n0 + r) * DD + tid];
    __syncthreads();

    int wid = tid >> 5, lane = tid & 31;
    for (int rr = 0; rr < 2; rr++) {
        int r = wid * 2 + rr;
        float s = 0.f, s2 = 0.f;
        #pragma unroll
        for (int i = 0; i < 8; i++) {
            float v = sY[r][lane * 8 + i];
            s += v; s2 += v * v;
        }
        #pragma unroll
        for (int o = 16; o; o >>= 1) {
            s  += __shfl_xor_sync(0xffffffffu, s, o);
            s2 += __shfl_xor_sync(0xffffffffu, s2, o);
        }
        if (lane == 0) {
            float mu = s * (1.0f / DD);
            sMu[r] = mu;
            sRs[r] = rsqrtf(s2 * (1.0f / DD) - mu * mu + EPSV);
        }
    }
    __syncthreads();
    float g = gamma[tid], bt = beta[tid];
    #pragma unroll
    for (int r = 0; r < 16; r++)
        out[((size_t)n0 + r) * DD + tid] = (sY[r][tid] - sMu[r]) * sRs[r] * g + bt;
}

// ---------------- launch ----------------------------------------------------
extern "C" void kernel_launch(void* const* d_in, const int* in_sizes, int n_in,
                              void* d_out, int out_size) {
    const float* x     = (const float*)d_in[0];
    const void*  mask  = d_in[1];
    const float* Wq    = (const float*)d_in[2];
    const float* Wk    = (const float*)d_in[3];
    const float* Wv    = (const float*)d_in[4];
    const float* Wo    = (const float*)d_in[5];
    const float* gamma = (const float*)d_in[6];
    const float* beta  = (const float*)d_in[7];
    float* out = (float*)d_out;

    mask_prep_kernel<<<1, 256>>>(mask);
    qkv_proj_kernel<<<dim3(NT / 64, HH, 3), 256>>>(x, Wq, Wk, Wv);
    score_kernel<<<dim3(512, HH, BB), 256>>>();
    spmax_av_kernel<<<NROWS / 8, 256>>>();   // FIX: cover all B*H*T rows
    outproj_ln_kernel<<<NT / 16, 256>>>(x, Wo, gamma, beta, out);
}